// round 2
// baseline (speedup 1.0000x reference)
#include <cuda_runtime.h>
#include <math.h>

// Problem constants
#define BB 4
#define TT 2048
#define HH 1024
#define NH 16
#define DD 64
#define ND 1024            // NH*DD
#define MM (BB*TT)         // 8192
// softmax uses exp2; fold scale*log2(e) into Q at load time
#define QSCALE 0.18033688f // (1/sqrt(64)) * log2(e)

// Scratch (device globals: allocation-free rule)
static __device__ float g_Q[MM * ND];
static __device__ float g_K[MM * ND];
static __device__ float g_V[MM * ND];
static __device__ float g_AO[MM * ND];

// ---------------------------------------------------------------------------
// SGEMM: C[M,N] = A[M,K] @ B[N,K]^T + bias[N]
// 128x128 tile, BK=16, 256 threads, 8x8 register block per thread.
// ---------------------------------------------------------------------------
__global__ __launch_bounds__(256, 2)
void gemm_abt_bias(const float* __restrict__ A, const float* __restrict__ Bw,
                   const float* __restrict__ bias, float* __restrict__ C,
                   int Kdim, int Ndim) {
    __shared__ float As[16][132];
    __shared__ float Bs[16][132];

    const int tid = threadIdx.x;
    const int tr = tid >> 4;          // 0..15
    const int tc = tid & 15;          // 0..15
    const int r0 = blockIdx.y * 128;
    const int c0 = blockIdx.x * 128;

    float acc[8][8];
#pragma unroll
    for (int i = 0; i < 8; i++)
#pragma unroll
        for (int j = 0; j < 8; j++) acc[i][j] = 0.0f;

    for (int k0 = 0; k0 < Kdim; k0 += 16) {
#pragma unroll
        for (int i = 0; i < 2; i++) {
            int idx = tid + i * 256;       // 0..511
            int row = idx >> 2;            // 0..127
            int kq  = (idx & 3) << 2;      // 0,4,8,12
            float4 va = *(const float4*)(A  + (size_t)(r0 + row) * Kdim + k0 + kq);
            As[kq + 0][row] = va.x; As[kq + 1][row] = va.y;
            As[kq + 2][row] = va.z; As[kq + 3][row] = va.w;
            float4 vb = *(const float4*)(Bw + (size_t)(c0 + row) * Kdim + k0 + kq);
            Bs[kq + 0][row] = vb.x; Bs[kq + 1][row] = vb.y;
            Bs[kq + 2][row] = vb.z; Bs[kq + 3][row] = vb.w;
        }
        __syncthreads();

#pragma unroll
        for (int kk = 0; kk < 16; kk++) {
            float a[8], b[8];
            *(float4*)(a)     = *(const float4*)&As[kk][tr * 8];
            *(float4*)(a + 4) = *(const float4*)&As[kk][tr * 8 + 4];
            *(float4*)(b)     = *(const float4*)&Bs[kk][tc * 8];
            *(float4*)(b + 4) = *(const float4*)&Bs[kk][tc * 8 + 4];
#pragma unroll
            for (int i = 0; i < 8; i++)
#pragma unroll
                for (int j = 0; j < 8; j++)
                    acc[i][j] += a[i] * b[j];
        }
        __syncthreads();
    }

#pragma unroll
    for (int i = 0; i < 8; i++) {
        size_t row = (size_t)(r0 + tr * 8 + i);
#pragma unroll
        for (int j = 0; j < 8; j += 4) {
            int c = c0 + tc * 8 + j;
            float4 o;
            o.x = acc[i][j + 0] + bias[c + 0];
            o.y = acc[i][j + 1] + bias[c + 1];
            o.z = acc[i][j + 2] + bias[c + 2];
            o.w = acc[i][j + 3] + bias[c + 3];
            *(float4*)(C + row * (size_t)Ndim + c) = o;
        }
    }
}

// ---------------------------------------------------------------------------
// Flash attention (fp32): one block = 128 queries of one (b, n).
// Q pre-scaled by (1/sqrt(D))*log2(e) at SMEM load; softmax uses exp2f.
// Threads: 256 as (tr 0..15, tc 0..15).
//   score phase: rows r = tr*8+rr (rr<8), cols c = tc + 16*cc (cc<4)
//   PV phase:    rows r = tr*8+rr, out dims d = tc*4+dd (dd<4)
// Row softmax state shared by the 16 tc-threads of a half-warp (shfl_xor <=8).
// ---------------------------------------------------------------------------
#define BQ 128
#define BS 64
#define SAT 68   // smem row stride (floats): 16B-aligned, <=2-way LDS conflicts

__global__ __launch_bounds__(256, 2)
void attn_kernel(const float* __restrict__ Qg, const float* __restrict__ Kg,
                 const float* __restrict__ Vg, float* __restrict__ Og) {
    extern __shared__ float sm[];
    float* Qs = sm;                       // [BQ][SAT]
    float* Ks = Qs + BQ * SAT;            // [BS][SAT]
    float* Vs = Ks + BS * SAT;            // [BS][SAT]
    float* Ps = Vs + BS * SAT;            // [BQ][SAT]

    const int tid = threadIdx.x;
    const int tr = tid >> 4;
    const int tc = tid & 15;
    const int b  = blockIdx.z;
    const int n  = blockIdx.y;
    const int q0 = blockIdx.x * BQ;

    const float* qbase = Qg + ((size_t)b * TT + q0) * ND + n * DD;
    const float* kbase = Kg + (size_t)b * TT * ND + n * DD;
    const float* vbase = Vg + (size_t)b * TT * ND + n * DD;

    // Load Q tile (128 rows x 64 floats), pre-scaled
#pragma unroll
    for (int i = 0; i < 8; i++) {
        int idx = tid + i * 256;
        int row = idx >> 4;
        int dq  = (idx & 15) << 2;
        float4 v = *(const float4*)(qbase + (size_t)row * ND + dq);
        v.x *= QSCALE; v.y *= QSCALE; v.z *= QSCALE; v.w *= QSCALE;
        *(float4*)&Qs[row * SAT + dq] = v;
    }

    float m[8], l[8], acc[8][4];
#pragma unroll
    for (int rr = 0; rr < 8; rr++) {
        m[rr] = -3.402823466e38f;
        l[rr] = 0.0f;
#pragma unroll
        for (int dd = 0; dd < 4; dd++) acc[rr][dd] = 0.0f;
    }

    for (int s0 = 0; s0 < TT; s0 += BS) {
        __syncthreads();  // previous PV done with Vs; also fences Qs on iter 0
#pragma unroll
        for (int i = 0; i < 4; i++) {
            int idx = tid + i * 256;
            int row = idx >> 4;
            int dq  = (idx & 15) << 2;
            *(float4*)&Ks[row * SAT + dq] =
                *(const float4*)(kbase + (size_t)(s0 + row) * ND + dq);
            *(float4*)&Vs[row * SAT + dq] =
                *(const float4*)(vbase + (size_t)(s0 + row) * ND + dq);
        }
        __syncthreads();

        // ---- scores (log2-domain): s[rr][cc] = qhat[r] . k[c] ----
        float s[8][4];
#pragma unroll
        for (int rr = 0; rr < 8; rr++)
#pragma unroll
            for (int cc = 0; cc < 4; cc++) s[rr][cc] = 0.0f;

#pragma unroll
        for (int d0 = 0; d0 < DD; d0 += 4) {
            float4 kv[4];
#pragma unroll
            for (int cc = 0; cc < 4; cc++)
                kv[cc] = *(const float4*)&Ks[(tc + 16 * cc) * SAT + d0];
#pragma unroll
            for (int rr = 0; rr < 8; rr++) {
                float4 qv = *(const float4*)&Qs[(tr * 8 + rr) * SAT + d0];
#pragma unroll
                for (int cc = 0; cc < 4; cc++) {
                    s[rr][cc] += qv.x * kv[cc].x;
                    s[rr][cc] += qv.y * kv[cc].y;
                    s[rr][cc] += qv.z * kv[cc].z;
                    s[rr][cc] += qv.w * kv[cc].w;
                }
            }
        }

        // ---- online softmax update (base-2) + write P ----
#pragma unroll
        for (int rr = 0; rr < 8; rr++) {
            float mx = s[rr][0];
#pragma unroll
            for (int cc = 1; cc < 4; cc++) mx = fmaxf(mx, s[rr][cc]);
#pragma unroll
            for (int off = 8; off > 0; off >>= 1)
                mx = fmaxf(mx, __shfl_xor_sync(0xffffffffu, mx, off));

            float mn = fmaxf(m[rr], mx);
            float f  = exp2f(m[rr] - mn);
            m[rr] = mn;

            float ls = 0.0f;
#pragma unroll
            for (int cc = 0; cc < 4; cc++) {
                float p = exp2f(s[rr][cc] - mn);
                s[rr][cc] = p;
                ls += p;
            }
#pragma unroll
            for (int off = 8; off > 0; off >>= 1)
                ls += __shfl_xor_sync(0xffffffffu, ls, off);

            l[rr] = l[rr] * f + ls;
#pragma unroll
            for (int dd = 0; dd < 4; dd++) acc[rr][dd] *= f;

#pragma unroll
            for (int cc = 0; cc < 4; cc++)
                Ps[(tr * 8 + rr) * SAT + tc + 16 * cc] = s[rr][cc];
        }
        __syncwarp();  // P rows are produced and consumed by the same half-warp

        // ---- PV: acc[rr][dd] += sum_j P[r][j] * V[j][tc*4+dd] ----
#pragma unroll
        for (int j0 = 0; j0 < BS; j0 += 4) {
            float4 vv[4];
#pragma unroll
            for (int jj = 0; jj < 4; jj++)
                vv[jj] = *(const float4*)&Vs[(j0 + jj) * SAT + tc * 4];
#pragma unroll
            for (int rr = 0; rr < 8; rr++) {
                float4 pv = *(const float4*)&Ps[(tr * 8 + rr) * SAT + j0];
                acc[rr][0] += pv.x * vv[0].x + pv.y * vv[1].x + pv.z * vv[2].x + pv.w * vv[3].x;
                acc[rr][1] += pv.x * vv[0].y + pv.y * vv[1].y + pv.z * vv[2].y + pv.w * vv[3].y;
                acc[rr][2] += pv.x * vv[0].z + pv.y * vv[1].z + pv.z * vv[2].z + pv.w * vv[3].z;
                acc[rr][3] += pv.x * vv[0].w + pv.y * vv[1].w + pv.z * vv[2].w + pv.w * vv[3].w;
            }
        }
    }

    // ---- epilogue: normalize and store ----
    float* obase = Og + ((size_t)b * TT + q0) * ND + n * DD;
#pragma unroll
    for (int rr = 0; rr < 8; rr++) {
        float inv = 1.0f / l[rr];
        float4 o;
        o.x = acc[rr][0] * inv;
        o.y = acc[rr][1] * inv;
        o.z = acc[rr][2] * inv;
        o.w = acc[rr][3] * inv;
        *(float4*)(obase + (size_t)(tr * 8 + rr) * ND + tc * 4) = o;
    }
}

// ---------------------------------------------------------------------------
// Launch
// ---------------------------------------------------------------------------
extern "C" void kernel_launch(void* const* d_in, const int* in_sizes, int n_in,
                              void* d_out, int out_size) {
    const float* query = (const float*)d_in[0];
    const float* value = (const float*)d_in[1];
    const float* Wq    = (const float*)d_in[2];
    const float* bq    = (const float*)d_in[3];
    const float* Wk    = (const float*)d_in[4];
    const float* bk    = (const float*)d_in[5];
    const float* Wv    = (const float*)d_in[6];
    const float* bv    = (const float*)d_in[7];
    const float* Wo    = (const float*)d_in[8];
    const float* bo    = (const float*)d_in[9];
    float* out = (float*)d_out;

    float *gq, *gk, *gv, *gao;
    cudaGetSymbolAddress((void**)&gq,  g_Q);
    cudaGetSymbolAddress((void**)&gk,  g_K);
    cudaGetSymbolAddress((void**)&gv,  g_V);
    cudaGetSymbolAddress((void**)&gao, g_AO);

    // Projections: [8192,1024] = in[8192,1024] @ W[1024,1024]^T + b
    dim3 pg(ND / 128, MM / 128);   // (8, 64)
    gemm_abt_bias<<<pg, 256>>>(query, Wq, bq, gq, HH, ND);
    gemm_abt_bias<<<pg, 256>>>(value, Wk, bk, gk, HH, ND);
    gemm_abt_bias<<<pg, 256>>>(value, Wv, bv, gv, HH, ND);

    // Attention
    size_t smem = (size_t)(BQ + BS + BS + BQ) * SAT * sizeof(float);  // ~102 KB
    cudaFuncSetAttribute(attn_kernel,
                         cudaFuncAttributeMaxDynamicSharedMemorySize, (int)smem);
    dim3 ag(TT / BQ, NH, BB);      // (16, 16, 4)
    attn_kernel<<<ag, 256, smem>>>(gq, gk, gv, gao);

    // Output projection: out[8192,1024] = AO @ Wo^T + bo
    dim3 og(HH / 128, MM / 128);
    gemm_abt_bias<<<og, 256>>>(gao, Wo, bo, out, ND, HH);
}

// round 6
// speedup vs baseline: 2.4110x; 2.4110x over previous
#include <cuda_runtime.h>
#include <cuda_bf16.h>
#include <math.h>
#include <stdint.h>

// Problem constants
#define BB 4
#define TT 2048
#define HH 1024
#define NH 16
#define DD 64
#define ND 1024            // NH*DD
#define MM (BB*TT)         // 8192
#define WSZ (1024*1024)
#define QSCALE 0.18033688f // (1/sqrt(64)) * log2(e)

// ---------------------------------------------------------------------------
// Scratch (device globals: allocation-free rule)
// ---------------------------------------------------------------------------
static __device__ __nv_bfloat16 g_inqh[MM * HH], g_inql[MM * HH];  // split(query)
static __device__ __nv_bfloat16 g_invh[MM * HH], g_invl[MM * HH];  // split(value)
static __device__ __nv_bfloat16 g_wh[4 * WSZ],   g_wl[4 * WSZ];    // Wq,Wk,Wv,Wo
static __device__ __nv_bfloat16 g_Qh[MM * ND], g_Ql[MM * ND];      // projected Q (pre-scaled)
static __device__ __nv_bfloat16 g_Kh[MM * ND], g_Kl[MM * ND];
static __device__ __nv_bfloat16 g_Vh[MM * ND], g_Vl[MM * ND];
static __device__ __nv_bfloat16 g_Oh[MM * ND], g_Ol[MM * ND];      // attention out

// ---------------------------------------------------------------------------
// PTX helpers (sm_80-class: mma.sync / ldmatrix / cp.async — legal on sm_100)
// ---------------------------------------------------------------------------
__device__ __forceinline__ uint32_t smem_u32(const void* p) {
    uint32_t a;
    asm("{ .reg .u64 t; cvta.to.shared.u64 t, %1; cvt.u32.u64 %0, t; }"
        : "=r"(a) : "l"(p));
    return a;
}
#define CP_ASYNC16(sa, g) \
    asm volatile("cp.async.cg.shared.global [%0], [%1], 16;" :: "r"(sa), "l"(g))
#define CP_COMMIT() asm volatile("cp.async.commit_group;")
#define CP_WAIT1()  asm volatile("cp.async.wait_group 1;")
#define CP_WAIT0()  asm volatile("cp.async.wait_group 0;")

#define LDSM_X4(r, addr) \
    asm volatile("ldmatrix.sync.aligned.m8n8.x4.shared.b16 {%0,%1,%2,%3}, [%4];" \
        : "=r"((r)[0]), "=r"((r)[1]), "=r"((r)[2]), "=r"((r)[3]) : "r"(addr))
#define LDSM_X2(r, addr) \
    asm volatile("ldmatrix.sync.aligned.m8n8.x2.shared.b16 {%0,%1}, [%2];" \
        : "=r"((r)[0]), "=r"((r)[1]) : "r"(addr))
#define LDSM_X2_T(r, addr) \
    asm volatile("ldmatrix.sync.aligned.m8n8.x2.trans.shared.b16 {%0,%1}, [%2];" \
        : "=r"((r)[0]), "=r"((r)[1]) : "r"(addr))

#define MMA_BF16(d, a, b) \
    asm volatile("mma.sync.aligned.m16n8k16.row.col.f32.bf16.bf16.f32 " \
        "{%0,%1,%2,%3}, {%4,%5,%6,%7}, {%8,%9}, {%0,%1,%2,%3};" \
        : "+f"((d)[0]), "+f"((d)[1]), "+f"((d)[2]), "+f"((d)[3]) \
        : "r"((a)[0]), "r"((a)[1]), "r"((a)[2]), "r"((a)[3]), \
          "r"((b)[0]), "r"((b)[1]))

__device__ __forceinline__ float ex2(float x) {
    float y;
    asm("ex2.approx.ftz.f32 %0, %1;" : "=f"(y) : "f"(x));
    return y;
}
// split two fp32 into packed bf16x2 hi + residual lo
__device__ __forceinline__ void split2(float x, float y, uint32_t& h, uint32_t& l) {
    float2 xy = make_float2(x, y);
    __nv_bfloat162 hh = __float22bfloat162_rn(xy);
    float2 hf = __bfloat1622float2(hh);
    __nv_bfloat162 ll = __float22bfloat162_rn(make_float2(x - hf.x, y - hf.y));
    h = *(uint32_t*)&hh;
    l = *(uint32_t*)&ll;
}

// ---------------------------------------------------------------------------
// fp32 -> bf16 hi/lo split (elementwise)
// ---------------------------------------------------------------------------
__global__ void convert_split(const float4* __restrict__ in,
                              uint2* __restrict__ hi, uint2* __restrict__ lo,
                              int n4) {
    int i = blockIdx.x * blockDim.x + threadIdx.x;
    if (i >= n4) return;
    float4 v = in[i];
    uint2 h, l;
    split2(v.x, v.y, h.x, l.x);
    split2(v.z, v.w, h.y, l.y);
    hi[i] = h;
    lo[i] = l;
}

// ---------------------------------------------------------------------------
// mma.sync split-bf16 GEMM: C = A[M,K] @ B[N,K]^T + bias, then * scale.
// Output either fp32 (Cf) or split-bf16 (Ch/Cl).
// CTA tile 128x128, BK=32, 8 warps (64x32 each), double-buffered cp.async.
// ---------------------------------------------------------------------------
#define STG   40960     // bytes per stage: Ah|Al|Bh|Bl, each 128 rows * 80B
#define MOFF  10240
#define GEMM_SMEM (2 * STG)

__global__ __launch_bounds__(256, 1)
void gemm_mma(const __nv_bfloat16* __restrict__ Ahp, const __nv_bfloat16* __restrict__ Alp,
              const __nv_bfloat16* __restrict__ Bhp, const __nv_bfloat16* __restrict__ Blp,
              const float* __restrict__ bias,
              float* __restrict__ Cf,
              __nv_bfloat16* __restrict__ Ch, __nv_bfloat16* __restrict__ Cl,
              float scale, int Kdim, int Ndim) {
    extern __shared__ __align__(128) char smem[];
    const uint32_t sbase = smem_u32(smem);
    const int tid  = threadIdx.x;
    const int lane = tid & 31;
    const int wid  = tid >> 5;
    const int warp_m = wid >> 2;
    const int warp_n = wid & 3;
    const int r0 = blockIdx.y * 128;
    const int c0 = blockIdx.x * 128;
    const int NCH = Kdim >> 5;

    float acc[4][4][4];
#pragma unroll
    for (int i = 0; i < 4; i++)
#pragma unroll
        for (int j = 0; j < 4; j++)
#pragma unroll
            for (int k = 0; k < 4; k++) acc[i][j][k] = 0.0f;

    auto load_chunk = [&](int c) {
        const int k0 = c << 5;
        const uint32_t st = sbase + (uint32_t)(c & 1) * STG;
#pragma unroll
        for (int m = 0; m < 4; m++) {
            const __nv_bfloat16* base =
                (m == 0) ? Ahp : (m == 1) ? Alp : (m == 2) ? Bhp : Blp;
            const int rb = (m < 2) ? r0 : c0;
#pragma unroll
            for (int i = 0; i < 2; i++) {
                int idx = tid + (i << 8);
                int row = idx >> 2;
                int c16 = idx & 3;
                const __nv_bfloat16* g =
                    base + (size_t)(rb + row) * Kdim + k0 + c16 * 8;
                uint32_t sa = st + (uint32_t)(m * MOFF + row * 80 + c16 * 16);
                CP_ASYNC16(sa, g);
            }
        }
        CP_COMMIT();
    };

    load_chunk(0);

    for (int c = 0; c < NCH; c++) {
        if (c + 1 < NCH) { load_chunk(c + 1); CP_WAIT1(); }
        else             { CP_WAIT0(); }
        __syncthreads();

        const uint32_t st = sbase + (uint32_t)(c & 1) * STG;
#pragma unroll
        for (int ks = 0; ks < 2; ks++) {
            const int kcolA = ks * 16 + ((lane >> 4) << 3);
            const int kcolB = ks * 16 + (((lane >> 3) & 1) << 3);
            uint32_t ah[4][4], al[4][4], bh[4][2], bl[4][2];
#pragma unroll
            for (int mf = 0; mf < 4; mf++) {
                uint32_t ra = st +
                    (uint32_t)((warp_m * 64 + mf * 16 + (lane & 15)) * 80 + kcolA * 2);
                LDSM_X4(ah[mf], ra);
                LDSM_X4(al[mf], ra + MOFF);
            }
#pragma unroll
            for (int nf = 0; nf < 4; nf++) {
                uint32_t rb = st + 2 * MOFF +
                    (uint32_t)((warp_n * 32 + nf * 8 + (lane & 7)) * 80 + kcolB * 2);
                LDSM_X2(bh[nf], rb);
                LDSM_X2(bl[nf], rb + MOFF);
            }
#pragma unroll
            for (int mf = 0; mf < 4; mf++)
#pragma unroll
                for (int nf = 0; nf < 4; nf++) {
                    MMA_BF16(acc[mf][nf], ah[mf], bh[nf]);
                    MMA_BF16(acc[mf][nf], ah[mf], bl[nf]);
                    MMA_BF16(acc[mf][nf], al[mf], bh[nf]);
                }
        }
        __syncthreads();
    }

    // ---- epilogue ----
#pragma unroll
    for (int mf = 0; mf < 4; mf++) {
        int row0 = r0 + warp_m * 64 + mf * 16 + (lane >> 2);
#pragma unroll
        for (int nf = 0; nf < 4; nf++) {
            int col = c0 + warp_n * 32 + nf * 8 + ((lane & 3) << 1);
            float2 bv = *(const float2*)&bias[col];
            float2 v0, v1;
            v0.x = (acc[mf][nf][0] + bv.x) * scale;
            v0.y = (acc[mf][nf][1] + bv.y) * scale;
            v1.x = (acc[mf][nf][2] + bv.x) * scale;
            v1.y = (acc[mf][nf][3] + bv.y) * scale;
            if (Cf) {
                *(float2*)&Cf[(size_t)row0 * Ndim + col] = v0;
                *(float2*)&Cf[(size_t)(row0 + 8) * Ndim + col] = v1;
            } else {
                uint32_t h0, l0, h1, l1;
                split2(v0.x, v0.y, h0, l0);
                split2(v1.x, v1.y, h1, l1);
                *(uint32_t*)&Ch[(size_t)row0 * Ndim + col] = h0;
                *(uint32_t*)&Cl[(size_t)row0 * Ndim + col] = l0;
                *(uint32_t*)&Ch[(size_t)(row0 + 8) * Ndim + col] = h1;
                *(uint32_t*)&Cl[(size_t)(row0 + 8) * Ndim + col] = l1;
            }
        }
    }
}

// ---------------------------------------------------------------------------
// FlashAttention-2 on mma.sync, split-bf16 everywhere.
// CTA = 128 q rows of one (b, n). 8 warps x m16. KV tiles of 64 rows,
// double-buffered cp.async. Softmax on fragments; P repacked in-register
// into A-fragments (C-frag -> A-frag identity). V via ldmatrix.trans.
// SMEM rows: 64 bf16 + 8 pad = 144B (stride = 16 mod 128: conflict-free).
// ---------------------------------------------------------------------------
#define AROW 144
#define QBYTES (128 * AROW)          // 18432 per matrix (Qh, Ql)
#define KVMAT  (64 * AROW)           // 9216 per matrix
#define KVSTG  (4 * KVMAT)           // Kh|Kl|Vh|Vl = 36864 per stage
#define ATTN_SMEM (2 * QBYTES + 2 * KVSTG)   // 110592

__global__ __launch_bounds__(256, 1)
void attn_mma(const __nv_bfloat16* __restrict__ Qhp, const __nv_bfloat16* __restrict__ Qlp,
              const __nv_bfloat16* __restrict__ Khp, const __nv_bfloat16* __restrict__ Klp,
              const __nv_bfloat16* __restrict__ Vhp, const __nv_bfloat16* __restrict__ Vlp,
              __nv_bfloat16* __restrict__ Ohp, __nv_bfloat16* __restrict__ Olp) {
    extern __shared__ __align__(128) char smem[];
    const uint32_t sbase = smem_u32(smem);
    const int tid  = threadIdx.x;
    const int lane = tid & 31;
    const int wid  = tid >> 5;
    const int b  = blockIdx.z;
    const int n  = blockIdx.y;
    const int q0 = blockIdx.x * 128;

    const size_t qrow0 = (size_t)b * TT + q0;
    const size_t krow0 = (size_t)b * TT;
    const int    cb    = n * DD;

    // ---- loaders ----
    auto load_q = [&]() {
        const __nv_bfloat16* srcs[2] = { Qhp, Qlp };
#pragma unroll
        for (int i = 0; i < 8; i++) {
            int idx = tid + (i << 8);          // < 2048
            int mat = idx >> 10;
            int row = (idx >> 3) & 127;
            int ch  = idx & 7;
            const __nv_bfloat16* g = srcs[mat] + (qrow0 + row) * ND + cb + ch * 8;
            uint32_t sa = sbase + (uint32_t)(mat * QBYTES + row * AROW + ch * 16);
            CP_ASYNC16(sa, g);
        }
    };
    auto load_kv = [&](int t) {
        const int s0 = t * 64;
        const __nv_bfloat16* srcs[4] = { Khp, Klp, Vhp, Vlp };
        const uint32_t st = sbase + 2 * QBYTES + (uint32_t)(t & 1) * KVSTG;
#pragma unroll
        for (int i = 0; i < 8; i++) {
            int idx = tid + (i << 8);          // < 2048
            int mat = idx >> 9;
            int row = (idx >> 3) & 63;
            int ch  = idx & 7;
            const __nv_bfloat16* g = srcs[mat] + (krow0 + s0 + row) * ND + cb + ch * 8;
            uint32_t sa = st + (uint32_t)(mat * KVMAT + row * AROW + ch * 16);
            CP_ASYNC16(sa, g);
        }
    };

    load_q();
    load_kv(0);
    CP_COMMIT();

    // softmax state (rows r = lane>>2 and r+8 within warp's m16)
    float m0 = -1e30f, m1 = -1e30f, l0 = 0.0f, l1 = 0.0f;
    float of[8][4];
#pragma unroll
    for (int d = 0; d < 8; d++)
#pragma unroll
        for (int k = 0; k < 4; k++) of[d][k] = 0.0f;

    uint32_t qfh[4][4], qfl[4][4];   // Q fragments, hoisted

    for (int t = 0; t < TT / 64; t++) {
        if (t + 1 < TT / 64) { load_kv(t + 1); CP_COMMIT(); CP_WAIT1(); }
        else                 { CP_WAIT0(); }
        __syncthreads();

        if (t == 0) {
            // hoist Q fragments: 4 ksteps (k=16 over D=64), h and l
#pragma unroll
            for (int ks = 0; ks < 4; ks++) {
                uint32_t ra = sbase +
                    (uint32_t)((wid * 16 + (lane & 15)) * AROW + ks * 32 + (lane >> 4) * 16);
                LDSM_X4(qfh[ks], ra);
                LDSM_X4(qfl[ks], ra + QBYTES);
            }
        }

        const uint32_t kvb = sbase + 2 * QBYTES + (uint32_t)(t & 1) * KVSTG;

        // ---- S = Q K^T (16 x 64), split 3-product ----
        float sf[8][4];
#pragma unroll
        for (int j = 0; j < 8; j++)
#pragma unroll
            for (int k = 0; k < 4; k++) sf[j][k] = 0.0f;

#pragma unroll
        for (int j = 0; j < 8; j++) {
#pragma unroll
            for (int ks = 0; ks < 4; ks++) {
                uint32_t rb = kvb +
                    (uint32_t)((j * 8 + (lane & 7)) * AROW + ks * 32 + ((lane >> 3) & 1) * 16);
                uint32_t bh[2], bl[2];
                LDSM_X2(bh, rb);
                LDSM_X2(bl, rb + KVMAT);
                MMA_BF16(sf[j], qfh[ks], bh);
                MMA_BF16(sf[j], qfh[ks], bl);
                MMA_BF16(sf[j], qfl[ks], bh);
            }
        }

        // ---- online softmax on fragments ----
        float mx0 = sf[0][0], mx1 = sf[0][2];
#pragma unroll
        for (int j = 0; j < 8; j++) {
            mx0 = fmaxf(mx0, fmaxf(sf[j][0], sf[j][1]));
            mx1 = fmaxf(mx1, fmaxf(sf[j][2], sf[j][3]));
        }
        mx0 = fmaxf(mx0, __shfl_xor_sync(0xffffffffu, mx0, 1));
        mx0 = fmaxf(mx0, __shfl_xor_sync(0xffffffffu, mx0, 2));
        mx1 = fmaxf(mx1, __shfl_xor_sync(0xffffffffu, mx1, 1));
        mx1 = fmaxf(mx1, __shfl_xor_sync(0xffffffffu, mx1, 2));

        float mn0 = fmaxf(m0, mx0), mn1 = fmaxf(m1, mx1);
        float f0 = ex2(m0 - mn0), f1 = ex2(m1 - mn1);
        m0 = mn0; m1 = mn1;

        float ls0 = 0.0f, ls1 = 0.0f;
#pragma unroll
        for (int j = 0; j < 8; j++) {
            sf[j][0] = ex2(sf[j][0] - mn0);
            sf[j][1] = ex2(sf[j][1] - mn0);
            sf[j][2] = ex2(sf[j][2] - mn1);
            sf[j][3] = ex2(sf[j][3] - mn1);
            ls0 += sf[j][0] + sf[j][1];
            ls1 += sf[j][2] + sf[j][3];
        }
        ls0 += __shfl_xor_sync(0xffffffffu, ls0, 1);
        ls0 += __shfl_xor_sync(0xffffffffu, ls0, 2);
        ls1 += __shfl_xor_sync(0xffffffffu, ls1, 1);
        ls1 += __shfl_xor_sync(0xffffffffu, ls1, 2);
        l0 = l0 * f0 + ls0;
        l1 = l1 * f1 + ls1;

#pragma unroll
        for (int d = 0; d < 8; d++) {
            of[d][0] *= f0; of[d][1] *= f0;
            of[d][2] *= f1; of[d][3] *= f1;
        }

        // ---- PV: O += P V (16 x 64 over k=64), split 3-product ----
        const uint32_t vbase = kvb + 2 * KVMAT;
#pragma unroll
        for (int sc = 0; sc < 4; sc++) {
            // build P A-frags for s-cols [16sc, 16sc+16): frag pair (2sc, 2sc+1)
            uint32_t pah[4], pal[4];
            split2(sf[2 * sc][0],     sf[2 * sc][1],     pah[0], pal[0]);
            split2(sf[2 * sc][2],     sf[2 * sc][3],     pah[1], pal[1]);
            split2(sf[2 * sc + 1][0], sf[2 * sc + 1][1], pah[2], pal[2]);
            split2(sf[2 * sc + 1][2], sf[2 * sc + 1][3], pah[3], pal[3]);
#pragma unroll
            for (int df = 0; df < 8; df++) {
                uint32_t va = vbase +
                    (uint32_t)((sc * 16 + (lane & 15)) * AROW + df * 16);
                uint32_t vh[2], vl[2];
                LDSM_X2_T(vh, va);
                LDSM_X2_T(vl, va + KVMAT);
                MMA_BF16(of[df], pah, vh);
                MMA_BF16(of[df], pah, vl);
                MMA_BF16(of[df], pal, vh);
            }
        }
        __syncthreads();
    }

    // ---- epilogue: normalize, split, store ----
    float inv0 = 1.0f / l0, inv1 = 1.0f / l1;
    size_t row_g0 = (qrow0 + wid * 16 + (lane >> 2)) * ND + cb + ((lane & 3) << 1);
#pragma unroll
    for (int df = 0; df < 8; df++) {
        uint32_t h0, lo0, h1, lo1;
        split2(of[df][0] * inv0, of[df][1] * inv0, h0, lo0);
        split2(of[df][2] * inv1, of[df][3] * inv1, h1, lo1);
        size_t p0 = row_g0 + df * 8;
        *(uint32_t*)&Ohp[p0] = h0;
        *(uint32_t*)&Olp[p0] = lo0;
        *(uint32_t*)&Ohp[p0 + 8 * ND] = h1;
        *(uint32_t*)&Olp[p0 + 8 * ND] = lo1;
    }
}

// ---------------------------------------------------------------------------
// Launch
// ---------------------------------------------------------------------------
extern "C" void kernel_launch(void* const* d_in, const int* in_sizes, int n_in,
                              void* d_out, int out_size) {
    const float* query = (const float*)d_in[0];
    const float* value = (const float*)d_in[1];
    const float* Wq    = (const float*)d_in[2];
    const float* bq    = (const float*)d_in[3];
    const float* Wk    = (const float*)d_in[4];
    const float* bk    = (const float*)d_in[5];
    const float* Wv    = (const float*)d_in[6];
    const float* bv    = (const float*)d_in[7];
    const float* Wo    = (const float*)d_in[8];
    const float* bo    = (const float*)d_in[9];
    float* out = (float*)d_out;

    __nv_bfloat16 *inqh, *inql, *invh, *invl, *wh, *wl;
    __nv_bfloat16 *Qh, *Ql, *Kh, *Kl, *Vh, *Vl, *Oh, *Ol;
    cudaGetSymbolAddress((void**)&inqh, g_inqh);
    cudaGetSymbolAddress((void**)&inql, g_inql);
    cudaGetSymbolAddress((void**)&invh, g_invh);
    cudaGetSymbolAddress((void**)&invl, g_invl);
    cudaGetSymbolAddress((void**)&wh,   g_wh);
    cudaGetSymbolAddress((void**)&wl,   g_wl);
    cudaGetSymbolAddress((void**)&Qh,   g_Qh);
    cudaGetSymbolAddress((void**)&Ql,   g_Ql);
    cudaGetSymbolAddress((void**)&Kh,   g_Kh);
    cudaGetSymbolAddress((void**)&Kl,   g_Kl);
    cudaGetSymbolAddress((void**)&Vh,   g_Vh);
    cudaGetSymbolAddress((void**)&Vl,   g_Vl);
    cudaGetSymbolAddress((void**)&Oh,   g_Oh);
    cudaGetSymbolAddress((void**)&Ol,   g_Ol);

    // input + weight splits
    {
        int n4 = MM * HH / 4;
        int gr = (n4 + 255) / 256;
        convert_split<<<gr, 256>>>((const float4*)query, (uint2*)inqh, (uint2*)inql, n4);
        convert_split<<<gr, 256>>>((const float4*)value, (uint2*)invh, (uint2*)invl, n4);
        int w4 = WSZ / 4;
        int gw = (w4 + 255) / 256;
        convert_split<<<gw, 256>>>((const float4*)Wq, (uint2*)(wh + 0 * WSZ), (uint2*)(wl + 0 * WSZ), w4);
        convert_split<<<gw, 256>>>((const float4*)Wk, (uint2*)(wh + 1 * WSZ), (uint2*)(wl + 1 * WSZ), w4);
        convert_split<<<gw, 256>>>((const float4*)Wv, (uint2*)(wh + 2 * WSZ), (uint2*)(wl + 2 * WSZ), w4);
        convert_split<<<gw, 256>>>((const float4*)Wo, (uint2*)(wh + 3 * WSZ), (uint2*)(wl + 3 * WSZ), w4);
    }

    cudaFuncSetAttribute(gemm_mma, cudaFuncAttributeMaxDynamicSharedMemorySize, GEMM_SMEM);
    dim3 pg(ND / 128, MM / 128);   // (8, 64)
    // Projections -> split bf16 directly; Q pre-scaled by QSCALE.
    gemm_mma<<<pg, 256, GEMM_SMEM>>>(inqh, inql, wh + 0 * WSZ, wl + 0 * WSZ, bq,
                                     nullptr, Qh, Ql, QSCALE, HH, ND);
    gemm_mma<<<pg, 256, GEMM_SMEM>>>(invh, invl, wh + 1 * WSZ, wl + 1 * WSZ, bk,
                                     nullptr, Kh, Kl, 1.0f, HH, ND);
    gemm_mma<<<pg, 256, GEMM_SMEM>>>(invh, invl, wh + 2 * WSZ, wl + 2 * WSZ, bv,
                                     nullptr, Vh, Vl, 1.0f, HH, ND);

    // Attention (tensor core)
    cudaFuncSetAttribute(attn_mma, cudaFuncAttributeMaxDynamicSharedMemorySize, ATTN_SMEM);
    dim3 ag(TT / 128, NH, BB);     // (16, 16, 4)
    attn_mma<<<ag, 256, ATTN_SMEM>>>(Qh, Ql, Kh, Kl, Vh, Vl, Oh, Ol);

    // Output projection -> fp32 out
    dim3 og(HH / 128, MM / 128);   // (8, 64)
    gemm_mma<<<og, 256, GEMM_SMEM>>>(Oh, Ol, wh + 3 * WSZ, wl + 3 * WSZ, bo,
                                     out, nullptr, nullptr, 1.0f, ND, HH);
}

// round 8
// speedup vs baseline: 2.4526x; 1.0172x over previous
#include <cuda_runtime.h>
#include <cuda_bf16.h>
#include <math.h>
#include <stdint.h>

// Problem constants
#define BB 4
#define TT 2048
#define HH 1024
#define NH 16
#define DD 64
#define ND 1024            // NH*DD
#define MM (BB*TT)         // 8192
#define WSZ (1024*1024)
#define QSCALE 0.18033688f // (1/sqrt(64)) * log2(e)

// ---------------------------------------------------------------------------
// Scratch (device globals: allocation-free rule)
// ---------------------------------------------------------------------------
static __device__ __nv_bfloat16 g_inqh[MM * HH], g_inql[MM * HH];  // split(query)
static __device__ __nv_bfloat16 g_invh[MM * HH], g_invl[MM * HH];  // split(value)
static __device__ __nv_bfloat16 g_wh[4 * WSZ],   g_wl[4 * WSZ];    // Wq,Wk,Wv,Wo
static __device__ __nv_bfloat16 g_Qh[MM * ND], g_Ql[MM * ND];      // projected Q (pre-scaled)
static __device__ __nv_bfloat16 g_Kh[MM * ND], g_Kl[MM * ND];
static __device__ __nv_bfloat16 g_Vh[MM * ND], g_Vl[MM * ND];
static __device__ __nv_bfloat16 g_Oh[MM * ND], g_Ol[MM * ND];      // attention out

// ---------------------------------------------------------------------------
// PTX helpers (sm_80-class: mma.sync / ldmatrix / cp.async — legal on sm_100)
// ---------------------------------------------------------------------------
__device__ __forceinline__ uint32_t smem_u32(const void* p) {
    uint32_t a;
    asm("{ .reg .u64 t; cvta.to.shared.u64 t, %1; cvt.u32.u64 %0, t; }"
        : "=r"(a) : "l"(p));
    return a;
}
#define CP_ASYNC16(sa, g) \
    asm volatile("cp.async.cg.shared.global [%0], [%1], 16;" :: "r"(sa), "l"(g))
#define CP_COMMIT() asm volatile("cp.async.commit_group;")
#define CP_WAIT1()  asm volatile("cp.async.wait_group 1;")
#define CP_WAIT0()  asm volatile("cp.async.wait_group 0;")

#define LDSM_X4(r, addr) \
    asm volatile("ldmatrix.sync.aligned.m8n8.x4.shared.b16 {%0,%1,%2,%3}, [%4];" \
        : "=r"((r)[0]), "=r"((r)[1]), "=r"((r)[2]), "=r"((r)[3]) : "r"(addr))
#define LDSM_X4_T(r, addr) \
    asm volatile("ldmatrix.sync.aligned.m8n8.x4.trans.shared.b16 {%0,%1,%2,%3}, [%4];" \
        : "=r"((r)[0]), "=r"((r)[1]), "=r"((r)[2]), "=r"((r)[3]) : "r"(addr))

#define MMA_BF16(d, a, b) \
    asm volatile("mma.sync.aligned.m16n8k16.row.col.f32.bf16.bf16.f32 " \
        "{%0,%1,%2,%3}, {%4,%5,%6,%7}, {%8,%9}, {%0,%1,%2,%3};" \
        : "+f"((d)[0]), "+f"((d)[1]), "+f"((d)[2]), "+f"((d)[3]) \
        : "r"((a)[0]), "r"((a)[1]), "r"((a)[2]), "r"((a)[3]), \
          "r"((b)[0]), "r"((b)[1]))

__device__ __forceinline__ float ex2(float x) {
    float y;
    asm("ex2.approx.ftz.f32 %0, %1;" : "=f"(y) : "f"(x));
    return y;
}
// split two fp32 into packed bf16x2 hi + residual lo
__device__ __forceinline__ void split2(float x, float y, uint32_t& h, uint32_t& l) {
    float2 xy = make_float2(x, y);
    __nv_bfloat162 hh = __float22bfloat162_rn(xy);
    float2 hf = __bfloat1622float2(hh);
    __nv_bfloat162 ll = __float22bfloat162_rn(make_float2(x - hf.x, y - hf.y));
    h = *(uint32_t*)&hh;
    l = *(uint32_t*)&ll;
}

// ---------------------------------------------------------------------------
// fp32 -> bf16 hi/lo split (elementwise, ILP=2)
// ---------------------------------------------------------------------------
__global__ void convert_split(const float4* __restrict__ in,
                              uint2* __restrict__ hi, uint2* __restrict__ lo,
                              int n4) {
    int i = (blockIdx.x * blockDim.x + threadIdx.x) * 2;
    if (i >= n4) return;
    float4 v0 = in[i];
    float4 v1 = in[i + 1];
    uint2 h0, l0, h1, l1;
    split2(v0.x, v0.y, h0.x, l0.x);
    split2(v0.z, v0.w, h0.y, l0.y);
    split2(v1.x, v1.y, h1.x, l1.x);
    split2(v1.z, v1.w, h1.y, l1.y);
    hi[i] = h0; hi[i + 1] = h1;
    lo[i] = l0; lo[i + 1] = l1;
}

// ---------------------------------------------------------------------------
// mma.sync split-bf16 GEMM: C = A[M,K] @ B[N,K]^T + bias, then * scale.
// Output either fp32 (Cf) or split-bf16 (Ch/Cl).
// CTA tile 128x128, BK=32, 8 warps (64x32 each), double-buffered cp.async.
// ---------------------------------------------------------------------------
#define STG   40960     // bytes per stage: Ah|Al|Bh|Bl, each 128 rows * 80B
#define MOFF  10240
#define GEMM_SMEM (2 * STG)

__global__ __launch_bounds__(256, 1)
void gemm_mma(const __nv_bfloat16* __restrict__ Ahp, const __nv_bfloat16* __restrict__ Alp,
              const __nv_bfloat16* __restrict__ Bhp, const __nv_bfloat16* __restrict__ Blp,
              const float* __restrict__ bias,
              float* __restrict__ Cf,
              __nv_bfloat16* __restrict__ Ch, __nv_bfloat16* __restrict__ Cl,
              float scale, int Kdim, int Ndim) {
    extern __shared__ __align__(128) char smem[];
    const uint32_t sbase = smem_u32(smem);
    const int tid  = threadIdx.x;
    const int lane = tid & 31;
    const int wid  = tid >> 5;
    const int warp_m = wid >> 2;
    const int warp_n = wid & 3;
    const int r0 = blockIdx.y * 128;
    const int c0 = blockIdx.x * 128;
    const int NCH = Kdim >> 5;

    float acc[4][4][4];
#pragma unroll
    for (int i = 0; i < 4; i++)
#pragma unroll
        for (int j = 0; j < 4; j++)
#pragma unroll
            for (int k = 0; k < 4; k++) acc[i][j][k] = 0.0f;

    auto load_chunk = [&](int c) {
        const int k0 = c << 5;
        const uint32_t st = sbase + (uint32_t)(c & 1) * STG;
#pragma unroll
        for (int m = 0; m < 4; m++) {
            const __nv_bfloat16* base =
                (m == 0) ? Ahp : (m == 1) ? Alp : (m == 2) ? Bhp : Blp;
            const int rb = (m < 2) ? r0 : c0;
#pragma unroll
            for (int i = 0; i < 2; i++) {
                int idx = tid + (i << 8);
                int row = idx >> 2;
                int c16 = idx & 3;
                const __nv_bfloat16* g =
                    base + (size_t)(rb + row) * Kdim + k0 + c16 * 8;
                uint32_t sa = st + (uint32_t)(m * MOFF + row * 80 + c16 * 16);
                CP_ASYNC16(sa, g);
            }
        }
        CP_COMMIT();
    };

    load_chunk(0);

    for (int c = 0; c < NCH; c++) {
        if (c + 1 < NCH) { load_chunk(c + 1); CP_WAIT1(); }
        else             { CP_WAIT0(); }
        __syncthreads();

        const uint32_t st = sbase + (uint32_t)(c & 1) * STG;
#pragma unroll
        for (int ks = 0; ks < 2; ks++) {
            const int kcolA = ks * 16 + ((lane >> 4) << 3);
            uint32_t ah[4][4], al[4][4], bh[2][4], bl[2][4];
#pragma unroll
            for (int mf = 0; mf < 4; mf++) {
                uint32_t ra = st +
                    (uint32_t)((warp_m * 64 + mf * 16 + (lane & 15)) * 80 + kcolA * 2);
                LDSM_X4(ah[mf], ra);
                LDSM_X4(al[mf], ra + MOFF);
            }
#pragma unroll
            for (int nfp = 0; nfp < 2; nfp++) {
                uint32_t rb = st + 2 * MOFF + (uint32_t)(
                    (warp_n * 32 + nfp * 16 + ((lane >> 4) << 3) + (lane & 7)) * 80 +
                    (ks * 16 + (((lane >> 3) & 1) << 3)) * 2);
                LDSM_X4(bh[nfp], rb);
                LDSM_X4(bl[nfp], rb + MOFF);
            }
#pragma unroll
            for (int mf = 0; mf < 4; mf++)
#pragma unroll
                for (int nf = 0; nf < 4; nf++) {
                    const uint32_t* bhp = bh[nf >> 1] + ((nf & 1) << 1);
                    const uint32_t* blp = bl[nf >> 1] + ((nf & 1) << 1);
                    MMA_BF16(acc[mf][nf], ah[mf], bhp);
                    MMA_BF16(acc[mf][nf], ah[mf], blp);
                    MMA_BF16(acc[mf][nf], al[mf], bhp);
                }
        }
        __syncthreads();
    }

    // ---- epilogue ----
#pragma unroll
    for (int mf = 0; mf < 4; mf++) {
        int row0 = r0 + warp_m * 64 + mf * 16 + (lane >> 2);
#pragma unroll
        for (int nf = 0; nf < 4; nf++) {
            int col = c0 + warp_n * 32 + nf * 8 + ((lane & 3) << 1);
            float2 bv = *(const float2*)&bias[col];
            float2 v0, v1;
            v0.x = (acc[mf][nf][0] + bv.x) * scale;
            v0.y = (acc[mf][nf][1] + bv.y) * scale;
            v1.x = (acc[mf][nf][2] + bv.x) * scale;
            v1.y = (acc[mf][nf][3] + bv.y) * scale;
            if (Cf) {
                *(float2*)&Cf[(size_t)row0 * Ndim + col] = v0;
                *(float2*)&Cf[(size_t)(row0 + 8) * Ndim + col] = v1;
            } else {
                uint32_t h0, l0, h1, l1;
                split2(v0.x, v0.y, h0, l0);
                split2(v1.x, v1.y, h1, l1);
                *(uint32_t*)&Ch[(size_t)row0 * Ndim + col] = h0;
                *(uint32_t*)&Cl[(size_t)row0 * Ndim + col] = l0;
                *(uint32_t*)&Ch[(size_t)(row0 + 8) * Ndim + col] = h1;
                *(uint32_t*)&Cl[(size_t)(row0 + 8) * Ndim + col] = l1;
            }
        }
    }
}

// ---------------------------------------------------------------------------
// FlashAttention-2 on mma.sync, split-bf16 everywhere.
// CTA = 128 q rows of one (b, n). 8 warps x m16. KV tiles of 64 rows,
// double-buffered cp.async. Softmax on fragments; P repacked in-register
// into A-fragments. K and V loaded via ldmatrix.x4 (two n8 blocks/instr).
// SMEM rows: 64 bf16 + 8 pad = 144B (stride = 16 mod 128: conflict-free).
// ---------------------------------------------------------------------------
#define AROW 144
#define QBYTES (128 * AROW)          // 18432 per matrix (Qh, Ql)
#define KVMAT  (64 * AROW)           // 9216 per matrix
#define KVSTG  (4 * KVMAT)           // Kh|Kl|Vh|Vl = 36864 per stage
#define ATTN_SMEM (2 * QBYTES + 2 * KVSTG)   // 110592

__global__ __launch_bounds__(256, 1)
void attn_mma(const __nv_bfloat16* __restrict__ Qhp, const __nv_bfloat16* __restrict__ Qlp,
              const __nv_bfloat16* __restrict__ Khp, const __nv_bfloat16* __restrict__ Klp,
              const __nv_bfloat16* __restrict__ Vhp, const __nv_bfloat16* __restrict__ Vlp,
              __nv_bfloat16* __restrict__ Ohp, __nv_bfloat16* __restrict__ Olp) {
    extern __shared__ __align__(128) char smem[];
    const uint32_t sbase = smem_u32(smem);
    const int tid  = threadIdx.x;
    const int lane = tid & 31;
    const int wid  = tid >> 5;
    const int b  = blockIdx.z;
    const int n  = blockIdx.y;
    const int q0 = blockIdx.x * 128;

    const size_t qrow0 = (size_t)b * TT + q0;
    const size_t krow0 = (size_t)b * TT;
    const int    cb    = n * DD;

    // ---- loaders ----
    auto load_q = [&]() {
        const __nv_bfloat16* srcs[2] = { Qhp, Qlp };
#pragma unroll
        for (int i = 0; i < 8; i++) {
            int idx = tid + (i << 8);          // < 2048
            int mat = idx >> 10;
            int row = (idx >> 3) & 127;
            int ch  = idx & 7;
            const __nv_bfloat16* g = srcs[mat] + (qrow0 + row) * ND + cb + ch * 8;
            uint32_t sa = sbase + (uint32_t)(mat * QBYTES + row * AROW + ch * 16);
            CP_ASYNC16(sa, g);
        }
    };
    auto load_kv = [&](int t) {
        const int s0 = t * 64;
        const __nv_bfloat16* srcs[4] = { Khp, Klp, Vhp, Vlp };
        const uint32_t st = sbase + 2 * QBYTES + (uint32_t)(t & 1) * KVSTG;
#pragma unroll
        for (int i = 0; i < 8; i++) {
            int idx = tid + (i << 8);          // < 2048
            int mat = idx >> 9;
            int row = (idx >> 3) & 63;
            int ch  = idx & 7;
            const __nv_bfloat16* g = srcs[mat] + (krow0 + s0 + row) * ND + cb + ch * 8;
            uint32_t sa = st + (uint32_t)(mat * KVMAT + row * AROW + ch * 16);
            CP_ASYNC16(sa, g);
        }
    };

    load_q();
    load_kv(0);
    CP_COMMIT();

    // softmax state (rows r = lane>>2 and r+8 within warp's m16)
    float m0 = -1e30f, m1 = -1e30f, l0 = 0.0f, l1 = 0.0f;
    float of[8][4];
#pragma unroll
    for (int d = 0; d < 8; d++)
#pragma unroll
        for (int k = 0; k < 4; k++) of[d][k] = 0.0f;

    uint32_t qfh[4][4], qfl[4][4];   // Q fragments, hoisted

    for (int t = 0; t < TT / 64; t++) {
        if (t + 1 < TT / 64) { load_kv(t + 1); CP_COMMIT(); CP_WAIT1(); }
        else                 { CP_WAIT0(); }
        __syncthreads();

        if (t == 0) {
            // hoist Q fragments: 4 ksteps (k=16 over D=64), h and l
#pragma unroll
            for (int ks = 0; ks < 4; ks++) {
                uint32_t ra = sbase +
                    (uint32_t)((wid * 16 + (lane & 15)) * AROW + ks * 32 + (lane >> 4) * 16);
                LDSM_X4(qfh[ks], ra);
                LDSM_X4(qfl[ks], ra + QBYTES);
            }
        }

        const uint32_t kvb = sbase + 2 * QBYTES + (uint32_t)(t & 1) * KVSTG;

        // ---- S = Q K^T (16 x 64), split 3-product, x4 K loads ----
        float sf[8][4];
#pragma unroll
        for (int j = 0; j < 8; j++)
#pragma unroll
            for (int k = 0; k < 4; k++) sf[j][k] = 0.0f;

#pragma unroll
        for (int jp = 0; jp < 4; jp++) {
#pragma unroll
            for (int ks = 0; ks < 4; ks++) {
                uint32_t rb = kvb + (uint32_t)(
                    (jp * 16 + ((lane >> 4) << 3) + (lane & 7)) * AROW +
                    ks * 32 + (((lane >> 3) & 1) << 4));
                uint32_t bh[4], bl[4];
                LDSM_X4(bh, rb);
                LDSM_X4(bl, rb + KVMAT);
                MMA_BF16(sf[2 * jp],     qfh[ks], bh);
                MMA_BF16(sf[2 * jp],     qfh[ks], bl);
                MMA_BF16(sf[2 * jp],     qfl[ks], bh);
                MMA_BF16(sf[2 * jp + 1], qfh[ks], bh + 2);
                MMA_BF16(sf[2 * jp + 1], qfh[ks], bl + 2);
                MMA_BF16(sf[2 * jp + 1], qfl[ks], bh + 2);
            }
        }

        // ---- online softmax on fragments ----
        float mx0 = sf[0][0], mx1 = sf[0][2];
#pragma unroll
        for (int j = 0; j < 8; j++) {
            mx0 = fmaxf(mx0, fmaxf(sf[j][0], sf[j][1]));
            mx1 = fmaxf(mx1, fmaxf(sf[j][2], sf[j][3]));
        }
        mx0 = fmaxf(mx0, __shfl_xor_sync(0xffffffffu, mx0, 1));
        mx0 = fmaxf(mx0, __shfl_xor_sync(0xffffffffu, mx0, 2));
        mx1 = fmaxf(mx1, __shfl_xor_sync(0xffffffffu, mx1, 1));
        mx1 = fmaxf(mx1, __shfl_xor_sync(0xffffffffu, mx1, 2));

        float mn0 = fmaxf(m0, mx0), mn1 = fmaxf(m1, mx1);
        float f0 = ex2(m0 - mn0), f1 = ex2(m1 - mn1);
        m0 = mn0; m1 = mn1;

        float ls0 = 0.0f, ls1 = 0.0f;
#pragma unroll
        for (int j = 0; j < 8; j++) {
            sf[j][0] = ex2(sf[j][0] - mn0);
            sf[j][1] = ex2(sf[j][1] - mn0);
            sf[j][2] = ex2(sf[j][2] - mn1);
            sf[j][3] = ex2(sf[j][3] - mn1);
            ls0 += sf[j][0] + sf[j][1];
            ls1 += sf[j][2] + sf[j][3];
        }
        ls0 += __shfl_xor_sync(0xffffffffu, ls0, 1);
        ls0 += __shfl_xor_sync(0xffffffffu, ls0, 2);
        ls1 += __shfl_xor_sync(0xffffffffu, ls1, 1);
        ls1 += __shfl_xor_sync(0xffffffffu, ls1, 2);
        l0 = l0 * f0 + ls0;
        l1 = l1 * f1 + ls1;

#pragma unroll
        for (int d = 0; d < 8; d++) {
            of[d][0] *= f0; of[d][1] *= f0;
            of[d][2] *= f1; of[d][3] *= f1;
        }

        // ---- PV: O += P V (16 x 64 over k=64), split 3-product, x4T V loads ----
        const uint32_t vbase = kvb + 2 * KVMAT;
#pragma unroll
        for (int sc = 0; sc < 4; sc++) {
            // build P A-frags for s-cols [16sc, 16sc+16)
            uint32_t pah[4], pal[4];
            split2(sf[2 * sc][0],     sf[2 * sc][1],     pah[0], pal[0]);
            split2(sf[2 * sc][2],     sf[2 * sc][3],     pah[1], pal[1]);
            split2(sf[2 * sc + 1][0], sf[2 * sc + 1][1], pah[2], pal[2]);
            split2(sf[2 * sc + 1][2], sf[2 * sc + 1][3], pah[3], pal[3]);
#pragma unroll
            for (int dfp = 0; dfp < 4; dfp++) {
                uint32_t va = vbase + (uint32_t)(
                    (sc * 16 + (((lane >> 3) & 1) << 3) + (lane & 7)) * AROW +
                    dfp * 32 + ((lane >> 4) << 4));
                uint32_t vh[4], vl[4];
                LDSM_X4_T(vh, va);
                LDSM_X4_T(vl, va + KVMAT);
                MMA_BF16(of[2 * dfp],     pah, vh);
                MMA_BF16(of[2 * dfp],     pah, vl);
                MMA_BF16(of[2 * dfp],     pal, vh);
                MMA_BF16(of[2 * dfp + 1], pah, vh + 2);
                MMA_BF16(of[2 * dfp + 1], pah, vl + 2);
                MMA_BF16(of[2 * dfp + 1], pal, vh + 2);
            }
        }
        __syncthreads();
    }

    // ---- epilogue: normalize, split, store ----
    float inv0 = 1.0f / l0, inv1 = 1.0f / l1;
    size_t row_g0 = (qrow0 + wid * 16 + (lane >> 2)) * ND + cb + ((lane & 3) << 1);
#pragma unroll
    for (int df = 0; df < 8; df++) {
        uint32_t h0, lo0, h1, lo1;
        split2(of[df][0] * inv0, of[df][1] * inv0, h0, lo0);
        split2(of[df][2] * inv1, of[df][3] * inv1, h1, lo1);
        size_t p0 = row_g0 + df * 8;
        *(uint32_t*)&Ohp[p0] = h0;
        *(uint32_t*)&Olp[p0] = lo0;
        *(uint32_t*)&Ohp[p0 + 8 * ND] = h1;
        *(uint32_t*)&Olp[p0 + 8 * ND] = lo1;
    }
}

// ---------------------------------------------------------------------------
// Launch
// ---------------------------------------------------------------------------
extern "C" void kernel_launch(void* const* d_in, const int* in_sizes, int n_in,
                              void* d_out, int out_size) {
    const float* query = (const float*)d_in[0];
    const float* value = (const float*)d_in[1];
    const float* Wq    = (const float*)d_in[2];
    const float* bq    = (const float*)d_in[3];
    const float* Wk    = (const float*)d_in[4];
    const float* bk    = (const float*)d_in[5];
    const float* Wv    = (const float*)d_in[6];
    const float* bv    = (const float*)d_in[7];
    const float* Wo    = (const float*)d_in[8];
    const float* bo    = (const float*)d_in[9];
    float* out = (float*)d_out;

    __nv_bfloat16 *inqh, *inql, *invh, *invl, *wh, *wl;
    __nv_bfloat16 *Qh, *Ql, *Kh, *Kl, *Vh, *Vl, *Oh, *Ol;
    cudaGetSymbolAddress((void**)&inqh, g_inqh);
    cudaGetSymbolAddress((void**)&inql, g_inql);
    cudaGetSymbolAddress((void**)&invh, g_invh);
    cudaGetSymbolAddress((void**)&invl, g_invl);
    cudaGetSymbolAddress((void**)&wh,   g_wh);
    cudaGetSymbolAddress((void**)&wl,   g_wl);
    cudaGetSymbolAddress((void**)&Qh,   g_Qh);
    cudaGetSymbolAddress((void**)&Ql,   g_Ql);
    cudaGetSymbolAddress((void**)&Kh,   g_Kh);
    cudaGetSymbolAddress((void**)&Kl,   g_Kl);
    cudaGetSymbolAddress((void**)&Vh,   g_Vh);
    cudaGetSymbolAddress((void**)&Vl,   g_Vl);
    cudaGetSymbolAddress((void**)&Oh,   g_Oh);
    cudaGetSymbolAddress((void**)&Ol,   g_Ol);

    // input + weight splits (ILP=2 -> half grid)
    {
        int n4 = MM * HH / 4;
        int gr = (n4 / 2 + 255) / 256;
        convert_split<<<gr, 256>>>((const float4*)query, (uint2*)inqh, (uint2*)inql, n4);
        convert_split<<<gr, 256>>>((const float4*)value, (uint2*)invh, (uint2*)invl, n4);
        int w4 = WSZ / 4;
        int gw = (w4 / 2 + 255) / 256;
        convert_split<<<gw, 256>>>((const float4*)Wq, (uint2*)(wh + 0 * WSZ), (uint2*)(wl + 0 * WSZ), w4);
        convert_split<<<gw, 256>>>((const float4*)Wk, (uint2*)(wh + 1 * WSZ), (uint2*)(wl + 1 * WSZ), w4);
        convert_split<<<gw, 256>>>((const float4*)Wv, (uint2*)(wh + 2 * WSZ), (uint2*)(wl + 2 * WSZ), w4);
        convert_split<<<gw, 256>>>((const float4*)Wo, (uint2*)(wh + 3 * WSZ), (uint2*)(wl + 3 * WSZ), w4);
    }

    cudaFuncSetAttribute(gemm_mma, cudaFuncAttributeMaxDynamicSharedMemorySize, GEMM_SMEM);
    dim3 pg(ND / 128, MM / 128);   // (8, 64)
    // Projections -> split bf16 directly; Q pre-scaled by QSCALE.
    gemm_mma<<<pg, 256, GEMM_SMEM>>>(inqh, inql, wh + 0 * WSZ, wl + 0 * WSZ, bq,
                                     nullptr, Qh, Ql, QSCALE, HH, ND);
    gemm_mma<<<pg, 256, GEMM_SMEM>>>(invh, invl, wh + 1 * WSZ, wl + 1 * WSZ, bk,
                                     nullptr, Kh, Kl, 1.0f, HH, ND);
    gemm_mma<<<pg, 256, GEMM_SMEM>>>(invh, invl, wh + 2 * WSZ, wl + 2 * WSZ, bv,
                                     nullptr, Vh, Vl, 1.0f, HH, ND);

    // Attention (tensor core)
    cudaFuncSetAttribute(attn_mma, cudaFuncAttributeMaxDynamicSharedMemorySize, ATTN_SMEM);
    dim3 ag(TT / 128, NH, BB);     // (16, 16, 4)
    attn_mma<<<ag, 256, ATTN_SMEM>>>(Qh, Ql, Kh, Kl, Vh, Vl, Oh, Ol);

    // Output projection -> fp32 out
    dim3 og(HH / 128, MM / 128);   // (8, 64)
    gemm_mma<<<og, 256, GEMM_SMEM>>>(Oh, Ol, wh + 3 * WSZ, wl + 3 * WSZ, bo,
                                     out, nullptr, nullptr, 1.0f, ND, HH);
}

// round 9
// speedup vs baseline: 2.5671x; 1.0467x over previous
#include <cuda_runtime.h>
#include <cuda_bf16.h>
#include <math.h>
#include <stdint.h>

// Problem constants
#define BB 4
#define TT 2048
#define HH 1024
#define NH 16
#define DD 64
#define ND 1024            // NH*DD
#define MM (BB*TT)         // 8192
#define WSZ (1024*1024)
#define QSCALE 0.18033688f // (1/sqrt(64)) * log2(e)

// ---------------------------------------------------------------------------
// Scratch (device globals: allocation-free rule)
// ---------------------------------------------------------------------------
static __device__ __nv_bfloat16 g_inqh[MM * HH], g_inql[MM * HH];  // split(query)
static __device__ __nv_bfloat16 g_invh[MM * HH], g_invl[MM * HH];  // split(value)
static __device__ __nv_bfloat16 g_wh[4 * WSZ],   g_wl[4 * WSZ];    // Wq,Wk,Wv,Wo
static __device__ __nv_bfloat16 g_Qh[MM * ND], g_Ql[MM * ND];      // projected Q (pre-scaled)
static __device__ __nv_bfloat16 g_Kh[MM * ND], g_Kl[MM * ND];
static __device__ __nv_bfloat16 g_Vh[MM * ND], g_Vl[MM * ND];
static __device__ __nv_bfloat16 g_Oh[MM * ND], g_Ol[MM * ND];      // attention out

// ---------------------------------------------------------------------------
// PTX helpers (sm_80-class: mma.sync / ldmatrix / cp.async — legal on sm_100)
// ---------------------------------------------------------------------------
__device__ __forceinline__ uint32_t smem_u32(const void* p) {
    uint32_t a;
    asm("{ .reg .u64 t; cvta.to.shared.u64 t, %1; cvt.u32.u64 %0, t; }"
        : "=r"(a) : "l"(p));
    return a;
}
#define CP_ASYNC16(sa, g) \
    asm volatile("cp.async.cg.shared.global [%0], [%1], 16;" :: "r"(sa), "l"(g))
#define CP_COMMIT() asm volatile("cp.async.commit_group;")
#define CP_WAIT1()  asm volatile("cp.async.wait_group 1;")
#define CP_WAIT0()  asm volatile("cp.async.wait_group 0;")

#define LDSM_X4(r, addr) \
    asm volatile("ldmatrix.sync.aligned.m8n8.x4.shared.b16 {%0,%1,%2,%3}, [%4];" \
        : "=r"((r)[0]), "=r"((r)[1]), "=r"((r)[2]), "=r"((r)[3]) : "r"(addr))
#define LDSM_X4_T(r, addr) \
    asm volatile("ldmatrix.sync.aligned.m8n8.x4.trans.shared.b16 {%0,%1,%2,%3}, [%4];" \
        : "=r"((r)[0]), "=r"((r)[1]), "=r"((r)[2]), "=r"((r)[3]) : "r"(addr))

#define MMA_BF16(d, a, b) \
    asm volatile("mma.sync.aligned.m16n8k16.row.col.f32.bf16.bf16.f32 " \
        "{%0,%1,%2,%3}, {%4,%5,%6,%7}, {%8,%9}, {%0,%1,%2,%3};" \
        : "+f"((d)[0]), "+f"((d)[1]), "+f"((d)[2]), "+f"((d)[3]) \
        : "r"((a)[0]), "r"((a)[1]), "r"((a)[2]), "r"((a)[3]), \
          "r"((b)[0]), "r"((b)[1]))

__device__ __forceinline__ float ex2(float x) {
    float y;
    asm("ex2.approx.ftz.f32 %0, %1;" : "=f"(y) : "f"(x));
    return y;
}
// split two fp32 into packed bf16x2 hi + residual lo
__device__ __forceinline__ void split2(float x, float y, uint32_t& h, uint32_t& l) {
    float2 xy = make_float2(x, y);
    __nv_bfloat162 hh = __float22bfloat162_rn(xy);
    float2 hf = __bfloat1622float2(hh);
    __nv_bfloat162 ll = __float22bfloat162_rn(make_float2(x - hf.x, y - hf.y));
    h = *(uint32_t*)&hh;
    l = *(uint32_t*)&ll;
}

// ---------------------------------------------------------------------------
// fp32 -> bf16 hi/lo split (elementwise, ILP=2)
// ---------------------------------------------------------------------------
__global__ void convert_split(const float4* __restrict__ in,
                              uint2* __restrict__ hi, uint2* __restrict__ lo,
                              int n4) {
    int i = (blockIdx.x * blockDim.x + threadIdx.x) * 2;
    if (i >= n4) return;
    float4 v0 = in[i];
    float4 v1 = in[i + 1];
    uint2 h0, l0, h1, l1;
    split2(v0.x, v0.y, h0.x, l0.x);
    split2(v0.z, v0.w, h0.y, l0.y);
    split2(v1.x, v1.y, h1.x, l1.x);
    split2(v1.z, v1.w, h1.y, l1.y);
    hi[i] = h0; hi[i + 1] = h1;
    lo[i] = l0; lo[i + 1] = l1;
}

// ---------------------------------------------------------------------------
// mma.sync split-bf16 GEMM: C = A[M,K] @ B[N,K]^T + bias, then * scale.
// Output either fp32 (Cf) or split-bf16 (Ch/Cl).
// CTA tile 128x128, BK=32, 8 warps (64x32 each), double-buffered cp.async.
// __launch_bounds__(256, 2): 2 CTAs/SM (160KB smem, <=128 regs) for latency
// hiding (4 warps/SMSP).
// ---------------------------------------------------------------------------
#define STG   40960     // bytes per stage: Ah|Al|Bh|Bl, each 128 rows * 80B
#define MOFF  10240
#define GEMM_SMEM (2 * STG)

__global__ __launch_bounds__(256, 2)
void gemm_mma(const __nv_bfloat16* __restrict__ Ahp, const __nv_bfloat16* __restrict__ Alp,
              const __nv_bfloat16* __restrict__ Bhp, const __nv_bfloat16* __restrict__ Blp,
              const float* __restrict__ bias,
              float* __restrict__ Cf,
              __nv_bfloat16* __restrict__ Ch, __nv_bfloat16* __restrict__ Cl,
              float scale, int Kdim, int Ndim) {
    extern __shared__ __align__(128) char smem[];
    const uint32_t sbase = smem_u32(smem);
    const int tid  = threadIdx.x;
    const int lane = tid & 31;
    const int wid  = tid >> 5;
    const int warp_m = wid >> 2;
    const int warp_n = wid & 3;
    const int r0 = blockIdx.y * 128;
    const int c0 = blockIdx.x * 128;
    const int NCH = Kdim >> 5;

    float acc[4][4][4];
#pragma unroll
    for (int i = 0; i < 4; i++)
#pragma unroll
        for (int j = 0; j < 4; j++)
#pragma unroll
            for (int k = 0; k < 4; k++) acc[i][j][k] = 0.0f;

    auto load_chunk = [&](int c) {
        const int k0 = c << 5;
        const uint32_t st = sbase + (uint32_t)(c & 1) * STG;
#pragma unroll
        for (int m = 0; m < 4; m++) {
            const __nv_bfloat16* base =
                (m == 0) ? Ahp : (m == 1) ? Alp : (m == 2) ? Bhp : Blp;
            const int rb = (m < 2) ? r0 : c0;
#pragma unroll
            for (int i = 0; i < 2; i++) {
                int idx = tid + (i << 8);
                int row = idx >> 2;
                int c16 = idx & 3;
                const __nv_bfloat16* g =
                    base + (size_t)(rb + row) * Kdim + k0 + c16 * 8;
                uint32_t sa = st + (uint32_t)(m * MOFF + row * 80 + c16 * 16);
                CP_ASYNC16(sa, g);
            }
        }
        CP_COMMIT();
    };

    load_chunk(0);

    for (int c = 0; c < NCH; c++) {
        if (c + 1 < NCH) { load_chunk(c + 1); CP_WAIT1(); }
        else             { CP_WAIT0(); }
        __syncthreads();

        const uint32_t st = sbase + (uint32_t)(c & 1) * STG;
#pragma unroll
        for (int ks = 0; ks < 2; ks++) {
            const int kcolA = ks * 16 + ((lane >> 4) << 3);
            uint32_t ah[4][4], al[4][4], bh[2][4], bl[2][4];
#pragma unroll
            for (int mf = 0; mf < 4; mf++) {
                uint32_t ra = st +
                    (uint32_t)((warp_m * 64 + mf * 16 + (lane & 15)) * 80 + kcolA * 2);
                LDSM_X4(ah[mf], ra);
                LDSM_X4(al[mf], ra + MOFF);
            }
#pragma unroll
            for (int nfp = 0; nfp < 2; nfp++) {
                uint32_t rb = st + 2 * MOFF + (uint32_t)(
                    (warp_n * 32 + nfp * 16 + ((lane >> 4) << 3) + (lane & 7)) * 80 +
                    (ks * 16 + (((lane >> 3) & 1) << 3)) * 2);
                LDSM_X4(bh[nfp], rb);
                LDSM_X4(bl[nfp], rb + MOFF);
            }
#pragma unroll
            for (int mf = 0; mf < 4; mf++)
#pragma unroll
                for (int nf = 0; nf < 4; nf++) {
                    const uint32_t* bhp = bh[nf >> 1] + ((nf & 1) << 1);
                    const uint32_t* blp = bl[nf >> 1] + ((nf & 1) << 1);
                    MMA_BF16(acc[mf][nf], ah[mf], bhp);
                    MMA_BF16(acc[mf][nf], ah[mf], blp);
                    MMA_BF16(acc[mf][nf], al[mf], bhp);
                }
        }
        __syncthreads();
    }

    // ---- epilogue ----
#pragma unroll
    for (int mf = 0; mf < 4; mf++) {
        int row0 = r0 + warp_m * 64 + mf * 16 + (lane >> 2);
#pragma unroll
        for (int nf = 0; nf < 4; nf++) {
            int col = c0 + warp_n * 32 + nf * 8 + ((lane & 3) << 1);
            float2 bv = *(const float2*)&bias[col];
            float2 v0, v1;
            v0.x = (acc[mf][nf][0] + bv.x) * scale;
            v0.y = (acc[mf][nf][1] + bv.y) * scale;
            v1.x = (acc[mf][nf][2] + bv.x) * scale;
            v1.y = (acc[mf][nf][3] + bv.y) * scale;
            if (Cf) {
                *(float2*)&Cf[(size_t)row0 * Ndim + col] = v0;
                *(float2*)&Cf[(size_t)(row0 + 8) * Ndim + col] = v1;
            } else {
                uint32_t h0, l0, h1, l1;
                split2(v0.x, v0.y, h0, l0);
                split2(v1.x, v1.y, h1, l1);
                *(uint32_t*)&Ch[(size_t)row0 * Ndim + col] = h0;
                *(uint32_t*)&Cl[(size_t)row0 * Ndim + col] = l0;
                *(uint32_t*)&Ch[(size_t)(row0 + 8) * Ndim + col] = h1;
                *(uint32_t*)&Cl[(size_t)(row0 + 8) * Ndim + col] = l1;
            }
        }
    }
}

// ---------------------------------------------------------------------------
// FlashAttention-2 on mma.sync, split-bf16 everywhere.
// CTA = 256 q rows of one (b, n). 16 warps x m16 (4 warps/SMSP for latency
// hiding). KV tiles of 64 rows, double-buffered cp.async. Softmax on
// fragments; P repacked in-register into A-fragments. K/V via ldmatrix.x4.
// SMEM rows: 64 bf16 + 8 pad = 144B. Total smem 147456 B.
// ---------------------------------------------------------------------------
#define ATHREADS 512
#define QROWS 256
#define AROW 144
#define QBYTES (QROWS * AROW)        // 36864 per matrix (Qh, Ql)
#define KVMAT  (64 * AROW)           // 9216 per matrix
#define KVSTG  (4 * KVMAT)           // Kh|Kl|Vh|Vl = 36864 per stage
#define ATTN_SMEM (2 * QBYTES + 2 * KVSTG)   // 147456

__global__ __launch_bounds__(ATHREADS, 1)
void attn_mma(const __nv_bfloat16* __restrict__ Qhp, const __nv_bfloat16* __restrict__ Qlp,
              const __nv_bfloat16* __restrict__ Khp, const __nv_bfloat16* __restrict__ Klp,
              const __nv_bfloat16* __restrict__ Vhp, const __nv_bfloat16* __restrict__ Vlp,
              __nv_bfloat16* __restrict__ Ohp, __nv_bfloat16* __restrict__ Olp) {
    extern __shared__ __align__(128) char smem[];
    const uint32_t sbase = smem_u32(smem);
    const int tid  = threadIdx.x;
    const int lane = tid & 31;
    const int wid  = tid >> 5;          // 0..15
    const int b  = blockIdx.z;
    const int n  = blockIdx.y;
    const int q0 = blockIdx.x * QROWS;

    const size_t qrow0 = (size_t)b * TT + q0;
    const size_t krow0 = (size_t)b * TT;
    const int    cb    = n * DD;

    // ---- loaders ----
    auto load_q = [&]() {
        const __nv_bfloat16* srcs[2] = { Qhp, Qlp };
#pragma unroll
        for (int i = 0; i < 8; i++) {
            int idx = tid + (i << 9);          // < 4096
            int mat = idx >> 11;
            int row = (idx >> 3) & 255;
            int ch  = idx & 7;
            const __nv_bfloat16* g = srcs[mat] + (qrow0 + row) * ND + cb + ch * 8;
            uint32_t sa = sbase + (uint32_t)(mat * QBYTES + row * AROW + ch * 16);
            CP_ASYNC16(sa, g);
        }
    };
    auto load_kv = [&](int t) {
        const int s0 = t * 64;
        const __nv_bfloat16* srcs[4] = { Khp, Klp, Vhp, Vlp };
        const uint32_t st = sbase + 2 * QBYTES + (uint32_t)(t & 1) * KVSTG;
#pragma unroll
        for (int i = 0; i < 4; i++) {
            int idx = tid + (i << 9);          // < 2048
            int mat = idx >> 9;
            int row = (idx >> 3) & 63;
            int ch  = idx & 7;
            const __nv_bfloat16* g = srcs[mat] + (krow0 + s0 + row) * ND + cb + ch * 8;
            uint32_t sa = st + (uint32_t)(mat * KVMAT + row * AROW + ch * 16);
            CP_ASYNC16(sa, g);
        }
    };

    load_q();
    load_kv(0);
    CP_COMMIT();

    // softmax state (rows r = lane>>2 and r+8 within warp's m16)
    float m0 = -1e30f, m1 = -1e30f, l0 = 0.0f, l1 = 0.0f;
    float of[8][4];
#pragma unroll
    for (int d = 0; d < 8; d++)
#pragma unroll
        for (int k = 0; k < 4; k++) of[d][k] = 0.0f;

    uint32_t qfh[4][4], qfl[4][4];   // Q fragments, hoisted

    for (int t = 0; t < TT / 64; t++) {
        if (t + 1 < TT / 64) { load_kv(t + 1); CP_COMMIT(); CP_WAIT1(); }
        else                 { CP_WAIT0(); }
        __syncthreads();

        if (t == 0) {
            // hoist Q fragments: 4 ksteps (k=16 over D=64), h and l
#pragma unroll
            for (int ks = 0; ks < 4; ks++) {
                uint32_t ra = sbase +
                    (uint32_t)((wid * 16 + (lane & 15)) * AROW + ks * 32 + (lane >> 4) * 16);
                LDSM_X4(qfh[ks], ra);
                LDSM_X4(qfl[ks], ra + QBYTES);
            }
        }

        const uint32_t kvb = sbase + 2 * QBYTES + (uint32_t)(t & 1) * KVSTG;

        // ---- S = Q K^T (16 x 64), split 3-product, x4 K loads ----
        float sf[8][4];
#pragma unroll
        for (int j = 0; j < 8; j++)
#pragma unroll
            for (int k = 0; k < 4; k++) sf[j][k] = 0.0f;

#pragma unroll
        for (int jp = 0; jp < 4; jp++) {
#pragma unroll
            for (int ks = 0; ks < 4; ks++) {
                uint32_t rb = kvb + (uint32_t)(
                    (jp * 16 + ((lane >> 4) << 3) + (lane & 7)) * AROW +
                    ks * 32 + (((lane >> 3) & 1) << 4));
                uint32_t bh[4], bl[4];
                LDSM_X4(bh, rb);
                LDSM_X4(bl, rb + KVMAT);
                MMA_BF16(sf[2 * jp],     qfh[ks], bh);
                MMA_BF16(sf[2 * jp],     qfh[ks], bl);
                MMA_BF16(sf[2 * jp],     qfl[ks], bh);
                MMA_BF16(sf[2 * jp + 1], qfh[ks], bh + 2);
                MMA_BF16(sf[2 * jp + 1], qfh[ks], bl + 2);
                MMA_BF16(sf[2 * jp + 1], qfl[ks], bh + 2);
            }
        }

        // ---- online softmax on fragments ----
        float mx0 = sf[0][0], mx1 = sf[0][2];
#pragma unroll
        for (int j = 0; j < 8; j++) {
            mx0 = fmaxf(mx0, fmaxf(sf[j][0], sf[j][1]));
            mx1 = fmaxf(mx1, fmaxf(sf[j][2], sf[j][3]));
        }
        mx0 = fmaxf(mx0, __shfl_xor_sync(0xffffffffu, mx0, 1));
        mx0 = fmaxf(mx0, __shfl_xor_sync(0xffffffffu, mx0, 2));
        mx1 = fmaxf(mx1, __shfl_xor_sync(0xffffffffu, mx1, 1));
        mx1 = fmaxf(mx1, __shfl_xor_sync(0xffffffffu, mx1, 2));

        float mn0 = fmaxf(m0, mx0), mn1 = fmaxf(m1, mx1);
        float f0 = ex2(m0 - mn0), f1 = ex2(m1 - mn1);
        m0 = mn0; m1 = mn1;

        float ls0 = 0.0f, ls1 = 0.0f;
#pragma unroll
        for (int j = 0; j < 8; j++) {
            sf[j][0] = ex2(sf[j][0] - mn0);
            sf[j][1] = ex2(sf[j][1] - mn0);
            sf[j][2] = ex2(sf[j][2] - mn1);
            sf[j][3] = ex2(sf[j][3] - mn1);
            ls0 += sf[j][0] + sf[j][1];
            ls1 += sf[j][2] + sf[j][3];
        }
        ls0 += __shfl_xor_sync(0xffffffffu, ls0, 1);
        ls0 += __shfl_xor_sync(0xffffffffu, ls0, 2);
        ls1 += __shfl_xor_sync(0xffffffffu, ls1, 1);
        ls1 += __shfl_xor_sync(0xffffffffu, ls1, 2);
        l0 = l0 * f0 + ls0;
        l1 = l1 * f1 + ls1;

#pragma unroll
        for (int d = 0; d < 8; d++) {
            of[d][0] *= f0; of[d][1] *= f0;
            of[d][2] *= f1; of[d][3] *= f1;
        }

        // ---- PV: O += P V (16 x 64 over k=64), split 3-product, x4T V loads ----
        const uint32_t vbase = kvb + 2 * KVMAT;
#pragma unroll
        for (int sc = 0; sc < 4; sc++) {
            // build P A-frags for s-cols [16sc, 16sc+16)
            uint32_t pah[4], pal[4];
            split2(sf[2 * sc][0],     sf[2 * sc][1],     pah[0], pal[0]);
            split2(sf[2 * sc][2],     sf[2 * sc][3],     pah[1], pal[1]);
            split2(sf[2 * sc + 1][0], sf[2 * sc + 1][1], pah[2], pal[2]);
            split2(sf[2 * sc + 1][2], sf[2 * sc + 1][3], pah[3], pal[3]);
#pragma unroll
            for (int dfp = 0; dfp < 4; dfp++) {
                uint32_t va = vbase + (uint32_t)(
                    (sc * 16 + (((lane >> 3) & 1) << 3) + (lane & 7)) * AROW +
                    dfp * 32 + ((lane >> 4) << 4));
                uint32_t vh[4], vl[4];
                LDSM_X4_T(vh, va);
                LDSM_X4_T(vl, va + KVMAT);
                MMA_BF16(of[2 * dfp],     pah, vh);
                MMA_BF16(of[2 * dfp],     pah, vl);
                MMA_BF16(of[2 * dfp],     pal, vh);
                MMA_BF16(of[2 * dfp + 1], pah, vh + 2);
                MMA_BF16(of[2 * dfp + 1], pah, vl + 2);
                MMA_BF16(of[2 * dfp + 1], pal, vh + 2);
            }
        }
        __syncthreads();
    }

    // ---- epilogue: normalize, split, store ----
    float inv0 = 1.0f / l0, inv1 = 1.0f / l1;
    size_t row_g0 = (qrow0 + wid * 16 + (lane >> 2)) * ND + cb + ((lane & 3) << 1);
#pragma unroll
    for (int df = 0; df < 8; df++) {
        uint32_t h0, lo0, h1, lo1;
        split2(of[df][0] * inv0, of[df][1] * inv0, h0, lo0);
        split2(of[df][2] * inv1, of[df][3] * inv1, h1, lo1);
        size_t p0 = row_g0 + df * 8;
        *(uint32_t*)&Ohp[p0] = h0;
        *(uint32_t*)&Olp[p0] = lo0;
        *(uint32_t*)&Ohp[p0 + 8 * ND] = h1;
        *(uint32_t*)&Olp[p0 + 8 * ND] = lo1;
    }
}

// ---------------------------------------------------------------------------
// Launch
// ---------------------------------------------------------------------------
extern "C" void kernel_launch(void* const* d_in, const int* in_sizes, int n_in,
                              void* d_out, int out_size) {
    const float* query = (const float*)d_in[0];
    const float* value = (const float*)d_in[1];
    const float* Wq    = (const float*)d_in[2];
    const float* bq    = (const float*)d_in[3];
    const float* Wk    = (const float*)d_in[4];
    const float* bk    = (const float*)d_in[5];
    const float* Wv    = (const float*)d_in[6];
    const float* bv    = (const float*)d_in[7];
    const float* Wo    = (const float*)d_in[8];
    const float* bo    = (const float*)d_in[9];
    float* out = (float*)d_out;

    __nv_bfloat16 *inqh, *inql, *invh, *invl, *wh, *wl;
    __nv_bfloat16 *Qh, *Ql, *Kh, *Kl, *Vh, *Vl, *Oh, *Ol;
    cudaGetSymbolAddress((void**)&inqh, g_inqh);
    cudaGetSymbolAddress((void**)&inql, g_inql);
    cudaGetSymbolAddress((void**)&invh, g_invh);
    cudaGetSymbolAddress((void**)&invl, g_invl);
    cudaGetSymbolAddress((void**)&wh,   g_wh);
    cudaGetSymbolAddress((void**)&wl,   g_wl);
    cudaGetSymbolAddress((void**)&Qh,   g_Qh);
    cudaGetSymbolAddress((void**)&Ql,   g_Ql);
    cudaGetSymbolAddress((void**)&Kh,   g_Kh);
    cudaGetSymbolAddress((void**)&Kl,   g_Kl);
    cudaGetSymbolAddress((void**)&Vh,   g_Vh);
    cudaGetSymbolAddress((void**)&Vl,   g_Vl);
    cudaGetSymbolAddress((void**)&Oh,   g_Oh);
    cudaGetSymbolAddress((void**)&Ol,   g_Ol);

    // input + weight splits (ILP=2 -> half grid)
    {
        int n4 = MM * HH / 4;
        int gr = (n4 / 2 + 255) / 256;
        convert_split<<<gr, 256>>>((const float4*)query, (uint2*)inqh, (uint2*)inql, n4);
        convert_split<<<gr, 256>>>((const float4*)value, (uint2*)invh, (uint2*)invl, n4);
        int w4 = WSZ / 4;
        int gw = (w4 / 2 + 255) / 256;
        convert_split<<<gw, 256>>>((const float4*)Wq, (uint2*)(wh + 0 * WSZ), (uint2*)(wl + 0 * WSZ), w4);
        convert_split<<<gw, 256>>>((const float4*)Wk, (uint2*)(wh + 1 * WSZ), (uint2*)(wl + 1 * WSZ), w4);
        convert_split<<<gw, 256>>>((const float4*)Wv, (uint2*)(wh + 2 * WSZ), (uint2*)(wl + 2 * WSZ), w4);
        convert_split<<<gw, 256>>>((const float4*)Wo, (uint2*)(wh + 3 * WSZ), (uint2*)(wl + 3 * WSZ), w4);
    }

    cudaFuncSetAttribute(gemm_mma, cudaFuncAttributeMaxDynamicSharedMemorySize, GEMM_SMEM);
    dim3 pg(ND / 128, MM / 128);   // (8, 64)
    // Projections -> split bf16 directly; Q pre-scaled by QSCALE.
    gemm_mma<<<pg, 256, GEMM_SMEM>>>(inqh, inql, wh + 0 * WSZ, wl + 0 * WSZ, bq,
                                     nullptr, Qh, Ql, QSCALE, HH, ND);
    gemm_mma<<<pg, 256, GEMM_SMEM>>>(invh, invl, wh + 1 * WSZ, wl + 1 * WSZ, bk,
                                     nullptr, Kh, Kl, 1.0f, HH, ND);
    gemm_mma<<<pg, 256, GEMM_SMEM>>>(invh, invl, wh + 2 * WSZ, wl + 2 * WSZ, bv,
                                     nullptr, Vh, Vl, 1.0f, HH, ND);

    // Attention (tensor core, 512 threads / 256 q-rows per CTA)
    cudaFuncSetAttribute(attn_mma, cudaFuncAttributeMaxDynamicSharedMemorySize, ATTN_SMEM);
    dim3 ag(TT / QROWS, NH, BB);   // (8, 16, 4)
    attn_mma<<<ag, ATHREADS, ATTN_SMEM>>>(Qh, Ql, Kh, Kl, Vh, Vl, Oh, Ol);

    // Output projection -> fp32 out
    dim3 og(HH / 128, MM / 128);   // (8, 64)
    gemm_mma<<<og, 256, GEMM_SMEM>>>(Oh, Ol, wh + 3 * WSZ, wl + 3 * WSZ, bo,
                                     out, nullptr, nullptr, 1.0f, ND, HH);
}